// round 4
// baseline (speedup 1.0000x reference)
#include <cuda_runtime.h>

// BayesianFlowNetworkDiscretised: per-element tiny MLP + discretised-bin CDF.
// R3: 4 elements/thread + packed float4 constant loads (kills the 64-LDS/elem
// bottleneck seen in R2's L1=57.5%).

constexpr int K = 16;
constexpr int H = 16;
constexpr int EPT = 4;           // elements per thread
constexpr int TPB = 256;

__device__ __forceinline__ float tanh_approx(float x) {
    float y;
    asm("tanh.approx.f32 %0, %1;" : "=f"(y) : "f"(x));
    return y;
}

// erf(x) ~= tanh(x * g(x^2)), g cubic, s-clamped for exact saturation.
#define ERF_C0 1.1283792f
#define ERF_C1 0.1038252f
#define ERF_C2 (-0.00176024f)
#define ERF_C3 (-2.46588e-5f)
#define ERF_SCAP 15.3664f

__device__ __forceinline__ void epilogue_store(
    float m, float acc0, float acc1,
    float inv_gamma, float vs, bool tmin,
    float* __restrict__ outp)
{
    float mu_x = fmaf(m, inv_gamma, -vs * acc0);
    float ln   = fminf(fmaxf(acc1, -10.0f), 10.0f);
    float sg   = fmaxf(vs * __expf(ln), 0.02f);
    if (tmin) { mu_x = 0.0f; sg = 1.0f; }

    const float inv  = __fdividef(0.70710678118654752f, sg);  // 1/(sigma*sqrt2)
    const float z1   = (-0.875f - mu_x) * inv;
    const float step = 0.125f * inv;

    float h[K - 1];
#pragma unroll
    for (int j = 0; j < K - 1; j++) {
        const float z = fmaf(step, (float)j, z1);
        float s = fminf(z * z, ERF_SCAP);
        const float p = fmaf(fmaf(fmaf(ERF_C3, s, ERF_C2), s, ERF_C1), s, ERF_C0);
        h[j] = 0.5f * tanh_approx(z * p);
    }

    float r[K];
    r[0] = h[0] + 0.5f;
#pragma unroll
    for (int j = 1; j < K - 1; j++) r[j] = h[j] - h[j - 1];
    r[K - 1] = 0.5f - h[K - 2];

    float4* o = reinterpret_cast<float4*>(outp);
    o[0] = make_float4(r[0],  r[1],  r[2],  r[3]);
    o[1] = make_float4(r[4],  r[5],  r[6],  r[7]);
    o[2] = make_float4(r[8],  r[9],  r[10], r[11]);
    o[3] = make_float4(r[12], r[13], r[14], r[15]);
}

__global__ __launch_bounds__(TPB) void bfn_kernel(
    const float* __restrict__ mu,
    const float* __restrict__ t,
    const float* __restrict__ W1,
    const float* __restrict__ b1,
    const float* __restrict__ W2,
    const float* __restrict__ b2,
    float* __restrict__ out,
    int Dn)
{
    __shared__ float4 s_pack[H];  // {W1[0][j], t*W1[1][j]+b1[j], .5*W2[j][0], .5*W2[j][1]}
    __shared__ float s_scal[8];   // inv_gamma, vs, tmin, a0, be0, a1, be1

    const int b = blockIdx.y;

    if (threadIdx.x < H) {
        const int j = threadIdx.x;
        const float tv = t[b];
        s_pack[j] = make_float4(W1[j],
                                fmaf(tv, W1[H + j], b1[j]),
                                0.5f * W2[2 * j],
                                0.5f * W2[2 * j + 1]);
        if (j == 0) {
            const float g = 1.0f - exp2f(2.0f * tv * -5.6438561897747395f);
            s_scal[0] = 1.0f / g;
            s_scal[1] = sqrtf((1.0f - g) / g);
            s_scal[2] = (tv < 1e-6f) ? 1.0f : 0.0f;
        }
    }
    __syncthreads();
    if (threadIdx.x == 0) {
        // fold linear half of tanh-gelu into per-row affine constants
        float a0 = b2[0], a1v = b2[1], be0 = 0.0f, be1 = 0.0f;
#pragma unroll
        for (int j = 0; j < H; j++) {
            const float4 p = s_pack[j];
            a0  = fmaf(p.y, p.z, a0);
            a1v = fmaf(p.y, p.w, a1v);
            be0 = fmaf(p.x, p.z, be0);
            be1 = fmaf(p.x, p.w, be1);
        }
        s_scal[3] = a0;  s_scal[4] = be0;
        s_scal[5] = a1v; s_scal[6] = be1;
    }
    __syncthreads();

    const float inv_gamma = s_scal[0];
    const float vs        = s_scal[1];
    const bool  tmin      = s_scal[2] > 0.5f;
    const float a0c  = s_scal[3], be0 = s_scal[4];
    const float a1c  = s_scal[5], be1 = s_scal[6];

    const int d0 = (blockIdx.x * TPB + threadIdx.x) * EPT;
    if (d0 >= Dn) return;
    const size_t base = (size_t)b * Dn + d0;

    if (d0 + EPT <= Dn) {
        const float4 mv = *reinterpret_cast<const float4*>(mu + base);
        float m[EPT] = {mv.x, mv.y, mv.z, mv.w};
        float acc0[EPT], acc1[EPT];
#pragma unroll
        for (int e = 0; e < EPT; e++) {
            acc0[e] = fmaf(m[e], be0, a0c);
            acc1[e] = fmaf(m[e], be1, a1c);
        }
#pragma unroll
        for (int j = 0; j < H; j++) {
            const float4 p = s_pack[j];
#pragma unroll
            for (int e = 0; e < EPT; e++) {
                const float a = fmaf(m[e], p.x, p.y);
                const float inner = a * fmaf(0.0356774081f, a * a, 0.7978845608f);
                const float ath = a * tanh_approx(inner);
                acc0[e] = fmaf(ath, p.z, acc0[e]);
                acc1[e] = fmaf(ath, p.w, acc1[e]);
            }
        }
#pragma unroll
        for (int e = 0; e < EPT; e++) {
            epilogue_store(m[e], acc0[e], acc1[e], inv_gamma, vs, tmin,
                           out + (base + e) * K);
        }
    } else {
        for (int e = 0; e < EPT && d0 + e < Dn; e++) {
            const float me = mu[base + e];
            float acc0 = fmaf(me, be0, a0c);
            float acc1 = fmaf(me, be1, a1c);
#pragma unroll
            for (int j = 0; j < H; j++) {
                const float4 p = s_pack[j];
                const float a = fmaf(me, p.x, p.y);
                const float inner = a * fmaf(0.0356774081f, a * a, 0.7978845608f);
                const float ath = a * tanh_approx(inner);
                acc0 = fmaf(ath, p.z, acc0);
                acc1 = fmaf(ath, p.w, acc1);
            }
            epilogue_store(me, acc0, acc1, inv_gamma, vs, tmin,
                           out + (base + e) * K);
        }
    }
}

extern "C" void kernel_launch(void* const* d_in, const int* in_sizes, int n_in,
                              void* d_out, int out_size) {
    const float* mu = (const float*)d_in[0];
    const float* t  = (const float*)d_in[1];
    const float* W1 = (const float*)d_in[2];
    const float* b1 = (const float*)d_in[3];
    const float* W2 = (const float*)d_in[4];
    const float* b2 = (const float*)d_in[5];
    float* out = (float*)d_out;

    const int B = in_sizes[1];           // t has B elements
    const int D = in_sizes[0] / B;       // mu is [B, D]

    dim3 grid((D + TPB * EPT - 1) / (TPB * EPT), B);
    bfn_kernel<<<grid, TPB>>>(mu, t, W1, b1, W2, b2, out, D);
}

// round 5
// speedup vs baseline: 1.6557x; 1.6557x over previous
#include <cuda_runtime.h>

// BayesianFlowNetworkDiscretised: per-element tiny MLP + discretised-bin CDF.
// R4: 1 elem/thread MLP (low regs), then warp-internal remap via shfl so each
// lane stores ONE consecutive float4 -> perfectly coalesced stores (fixes the
// store-wavefront amplification that capped R2/R3 at L1~56%).

constexpr int K = 16;
constexpr int H = 16;
constexpr int TPB = 256;

__device__ __forceinline__ float tanh_approx(float x) {
    float y;
    asm("tanh.approx.f32 %0, %1;" : "=f"(y) : "f"(x));
    return y;
}

// erf(x) ~= tanh(x * g(x^2)), g cubic, s-clamped for exact saturation (~7e-5 abs).
#define ERF_C0 1.1283792f
#define ERF_C1 0.1038252f
#define ERF_C2 (-0.00176024f)
#define ERF_C3 (-2.46588e-5f)
#define ERF_SCAP 15.3664f

__device__ __forceinline__ float erf_fast(float z) {
    const float s = fminf(z * z, ERF_SCAP);
    const float p = fmaf(fmaf(fmaf(ERF_C3, s, ERF_C2), s, ERF_C1), s, ERF_C0);
    return tanh_approx(z * p);
}

__global__ __launch_bounds__(TPB) void bfn_kernel(
    const float* __restrict__ mu,
    const float* __restrict__ t,
    const float* __restrict__ W1,
    const float* __restrict__ b1,
    const float* __restrict__ W2,
    const float* __restrict__ b2,
    float* __restrict__ out,
    int Dn)
{
    __shared__ float4 s_pack[H];  // {W1[0][j], t*W1[1][j]+b1[j], .5*W2[j][0], .5*W2[j][1]}
    __shared__ float s_scal[8];   // inv_gamma, vs, tmin, a0, be0, a1, be1

    const int b = blockIdx.y;

    if (threadIdx.x < H) {
        const int j = threadIdx.x;
        const float tv = t[b];
        s_pack[j] = make_float4(W1[j],
                                fmaf(tv, W1[H + j], b1[j]),
                                0.5f * W2[2 * j],
                                0.5f * W2[2 * j + 1]);
        if (j == 0) {
            const float g = 1.0f - exp2f(2.0f * tv * -5.6438561897747395f);
            s_scal[0] = 1.0f / g;
            s_scal[1] = sqrtf((1.0f - g) / g);
            s_scal[2] = (tv < 1e-6f) ? 1.0f : 0.0f;
        }
    }
    __syncthreads();
    if (threadIdx.x == 0) {
        // fold linear half of tanh-gelu into per-row affine constants
        float a0 = b2[0], a1v = b2[1], be0 = 0.0f, be1 = 0.0f;
#pragma unroll
        for (int j = 0; j < H; j++) {
            const float4 p = s_pack[j];
            a0  = fmaf(p.y, p.z, a0);
            a1v = fmaf(p.y, p.w, a1v);
            be0 = fmaf(p.x, p.z, be0);
            be1 = fmaf(p.x, p.w, be1);
        }
        s_scal[3] = a0;  s_scal[4] = be0;
        s_scal[5] = a1v; s_scal[6] = be1;
    }
    __syncthreads();

    const float inv_gamma = s_scal[0];
    const float vs        = s_scal[1];
    const bool  tmin      = s_scal[2] > 0.5f;

    const int d = blockIdx.x * TPB + threadIdx.x;
    if (d >= Dn) return;

    const size_t elem = (size_t)b * Dn + d;
    const float m = mu[elem];

    // ---- phase 1: tiny MLP (tanh-gelu) -> (zbase, step) ----
    float acc0 = fmaf(m, s_scal[4], s_scal[3]);
    float acc1 = fmaf(m, s_scal[6], s_scal[5]);
#pragma unroll
    for (int j = 0; j < H; j++) {
        const float4 p = s_pack[j];
        const float a = fmaf(m, p.x, p.y);
        const float inner = a * fmaf(0.0356774081f, a * a, 0.7978845608f);
        const float ath = a * tanh_approx(inner);
        acc0 = fmaf(ath, p.z, acc0);
        acc1 = fmaf(ath, p.w, acc1);
    }

    float mu_x = fmaf(m, inv_gamma, -vs * acc0);
    float ln   = fminf(fmaxf(acc1, -10.0f), 10.0f);
    float sg   = fmaxf(vs * __expf(ln), 0.02f);
    if (tmin) { mu_x = 0.0f; sg = 1.0f; }

    const float inv   = __fdividef(0.70710678118654752f, sg);  // 1/(sigma*sqrt2)
    const float zbase = (-1.0f - mu_x) * inv;  // boundary k: z = zbase + k*step/ (k=0..16)
    const float step  = 0.125f * inv;

    // ---- phase 2: warp-transposed epilogue, coalesced float4 stores ----
    const int lane = threadIdx.x & 31;
    const int warp_d0 = d - lane;                    // first elem of this warp
    const bool full = (warp_d0 + 32 <= Dn);
    const size_t wbase = ((size_t)b * Dn + warp_d0) * K;

    if (full) {
        const int q = lane & 3;               // bin-quad 0..3
        const float kb = (float)(4 * q);      // boundary base index
#pragma unroll
        for (int it = 0; it < 4; it++) {
            const int e_l = it * 8 + (lane >> 2);   // source lane (element owner)
            const float zb = __shfl_sync(0xffffffffu, zbase, e_l);
            const float st = __shfl_sync(0xffffffffu, step,  e_l);

            // boundaries 4q+1 .. 4q+4
            float e1 = erf_fast(fmaf(st, kb + 1.0f, zb));
            float e2 = erf_fast(fmaf(st, kb + 2.0f, zb));
            float e3 = erf_fast(fmaf(st, kb + 3.0f, zb));
            float e4 = erf_fast(fmaf(st, kb + 4.0f, zb));
            if (q == 3) e4 = 1.0f;            // upper edge exact (+1)
            // lower boundary 4q: from neighbor lane's e4; quad 0 edge exact (-1)
            float e0 = __shfl_up_sync(0xffffffffu, e4, 1);
            if (q == 0) e0 = -1.0f;

            const float4 r = make_float4(0.5f * (e1 - e0),
                                         0.5f * (e2 - e1),
                                         0.5f * (e3 - e2),
                                         0.5f * (e4 - e3));
            // consecutive: lane l writes float4 #(it*32 + l) of the warp's 2KB tile
            reinterpret_cast<float4*>(out + wbase)[it * 32 + lane] = r;
        }
    } else {
        // tail warp: plain per-thread scatter (correctness path, rarely taken)
        float h[K - 1];
#pragma unroll
        for (int j = 0; j < K - 1; j++)
            h[j] = 0.5f * erf_fast(fmaf(step, (float)(j + 1), zbase));
        float r[K];
        r[0] = h[0] + 0.5f;
#pragma unroll
        for (int j = 1; j < K - 1; j++) r[j] = h[j] - h[j - 1];
        r[K - 1] = 0.5f - h[K - 2];
        float4* o = reinterpret_cast<float4*>(out + elem * K);
        o[0] = make_float4(r[0],  r[1],  r[2],  r[3]);
        o[1] = make_float4(r[4],  r[5],  r[6],  r[7]);
        o[2] = make_float4(r[8],  r[9],  r[10], r[11]);
        o[3] = make_float4(r[12], r[13], r[14], r[15]);
    }
}

extern "C" void kernel_launch(void* const* d_in, const int* in_sizes, int n_in,
                              void* d_out, int out_size) {
    const float* mu = (const float*)d_in[0];
    const float* t  = (const float*)d_in[1];
    const float* W1 = (const float*)d_in[2];
    const float* b1 = (const float*)d_in[3];
    const float* W2 = (const float*)d_in[4];
    const float* b2 = (const float*)d_in[5];
    float* out = (float*)d_out;

    const int B = in_sizes[1];           // t has B elements
    const int D = in_sizes[0] / B;       // mu is [B, D]

    dim3 grid((D + TPB - 1) / TPB, B);
    bfn_kernel<<<grid, TPB>>>(mu, t, W1, b1, W2, b2, out, D);
}

// round 6
// speedup vs baseline: 2.4115x; 1.4565x over previous
#include <cuda_runtime.h>

// BayesianFlowNetworkDiscretised: per-element tiny MLP + discretised-bin CDF.
// R5: phase-1 as R2 (best issue count); phase-2 remaps via smem (zbase,step)
// so each lane stores ONE consecutive float4 (coalesced), boundary shared by a
// single fixed-delta shfl_up. erf poly reduced to quadratic (max err 2.2e-4).

constexpr int K = 16;
constexpr int H = 16;
constexpr int TPB = 256;

__device__ __forceinline__ float tanh_approx(float x) {
    float y;
    asm("tanh.approx.f32 %0, %1;" : "=f"(y) : "f"(x));
    return y;
}

// erf(z) ~= tanh(z * (C0 + C1 s + C2 s^2)), s = min(z^2, SCAP); max abs err ~2.2e-4
#define EQ_C0 1.1283792f
#define EQ_C1 0.104519f
#define EQ_C2 (-0.0020913f)
#define EQ_SCAP 22.0f

__device__ __forceinline__ float erf_q(float z) {
    const float s = fminf(z * z, EQ_SCAP);
    const float p = fmaf(fmaf(EQ_C2, s, EQ_C1), s, EQ_C0);
    return tanh_approx(z * p);
}

__global__ __launch_bounds__(TPB) void bfn_kernel(
    const float* __restrict__ mu,
    const float* __restrict__ t,
    const float* __restrict__ W1,
    const float* __restrict__ b1,
    const float* __restrict__ W2,
    const float* __restrict__ b2,
    float* __restrict__ out,
    int Dn)
{
    __shared__ float4 s_pack[H];   // {W1[0][j], t*W1[1][j]+b1[j], .5*W2[j][0], .5*W2[j][1]}
    __shared__ float  s_scal[8];   // inv_gamma, vs, tmin, a0, be0, a1, be1
    __shared__ float2 s_zs[TPB];   // per-element (zbase, step)

    const int b = blockIdx.y;

    if (threadIdx.x < H) {
        const int j = threadIdx.x;
        const float tv = t[b];
        s_pack[j] = make_float4(W1[j],
                                fmaf(tv, W1[H + j], b1[j]),
                                0.5f * W2[2 * j],
                                0.5f * W2[2 * j + 1]);
        if (j == 0) {
            const float g = 1.0f - exp2f(2.0f * tv * -5.6438561897747395f);
            s_scal[0] = 1.0f / g;
            s_scal[1] = sqrtf((1.0f - g) / g);
            s_scal[2] = (tv < 1e-6f) ? 1.0f : 0.0f;
        }
    }
    __syncthreads();
    if (threadIdx.x == 0) {
        // fold the linear half of tanh-gelu into per-row affine constants
        float a0 = b2[0], a1v = b2[1], be0 = 0.0f, be1 = 0.0f;
#pragma unroll
        for (int j = 0; j < H; j++) {
            const float4 p = s_pack[j];
            a0  = fmaf(p.y, p.z, a0);
            a1v = fmaf(p.y, p.w, a1v);
            be0 = fmaf(p.x, p.z, be0);
            be1 = fmaf(p.x, p.w, be1);
        }
        s_scal[3] = a0;  s_scal[4] = be0;
        s_scal[5] = a1v; s_scal[6] = be1;
    }
    __syncthreads();

    const float inv_gamma = s_scal[0];
    const float vs        = s_scal[1];
    const bool  tmin      = s_scal[2] > 0.5f;

    const int d = blockIdx.x * TPB + threadIdx.x;
    const bool active = (d < Dn);
    const int dclamp = active ? d : (Dn - 1);
    const float m = mu[(size_t)b * Dn + dclamp];

    // ---- phase 1: tiny MLP (tanh-gelu) -> (zbase, step) ----
    float acc0 = fmaf(m, s_scal[4], s_scal[3]);
    float acc1 = fmaf(m, s_scal[6], s_scal[5]);
#pragma unroll
    for (int j = 0; j < H; j++) {
        const float4 p = s_pack[j];
        const float a = fmaf(m, p.x, p.y);
        const float inner = a * fmaf(0.0356774081f, a * a, 0.7978845608f);
        const float ath = a * tanh_approx(inner);
        acc0 = fmaf(ath, p.z, acc0);
        acc1 = fmaf(ath, p.w, acc1);
    }

    float mu_x = fmaf(m, inv_gamma, -vs * acc0);
    float ln   = fminf(fmaxf(acc1, -10.0f), 10.0f);
    float sg   = fmaxf(vs * __expf(ln), 0.02f);
    if (tmin) { mu_x = 0.0f; sg = 1.0f; }

    const float inv   = __fdividef(0.70710678118654752f, sg);  // 1/(sigma*sqrt2)
    const float zbase = (-1.0f - mu_x) * inv;   // boundary j: z = zbase + j*step, j=0..16
    const float step  = 0.125f * inv;

    // ---- phase 2: smem remap, coalesced stores ----
    const int lane    = threadIdx.x & 31;
    const int wbase_t = threadIdx.x & ~31;               // warp's first thread in block
    const int warp_d0 = blockIdx.x * TPB + wbase_t;

    s_zs[threadIdx.x] = make_float2(zbase, step);
    __syncwarp();

    if (warp_d0 + 32 <= Dn) {
        const int q = lane & 3;                          // bin-quad 0..3
        const float kq = (float)(q << 2);
        const float k1 = kq + 1.0f, k2 = kq + 2.0f, k3 = kq + 3.0f, k4 = kq + 4.0f;
        const bool q0 = (q == 0), q3 = (q == 3);
        // lane l writes float4 #(it*32 + l) of the warp's 2KB output tile
        float4* wout = reinterpret_cast<float4*>(out)
                     + ((size_t)b * Dn + warp_d0) * 4 + lane;
        const int src = wbase_t + (lane >> 2);           // element owner (+ it*8)

#pragma unroll
        for (int it = 0; it < 4; it++) {
            const float2 zs = s_zs[src + it * 8];
            const float zb = zs.x, st = zs.y;

            const float e1 = erf_q(fmaf(st, k1, zb));
            const float e2 = erf_q(fmaf(st, k2, zb));
            const float e3 = erf_q(fmaf(st, k3, zb));
            const float e4 = erf_q(fmaf(st, k4, zb));

            const float h1 = 0.5f * e1;
            const float h2 = 0.5f * e2;
            const float h3 = 0.5f * e3;
            float h4 = q3 ? 0.5f : 0.5f * e4;            // upper edge exact

            const float hup = __shfl_up_sync(0xffffffffu, h4, 1);
            const float h0 = q0 ? -0.5f : hup;           // lower edge exact

            wout[it * 32] = make_float4(h1 - h0, h2 - h1, h3 - h2, h4 - h3);
        }
    } else if (active) {
        // tail warp: per-thread scatter (correctness path; D%32==0 -> not taken)
        float h[K - 1];
#pragma unroll
        for (int j = 0; j < K - 1; j++)
            h[j] = 0.5f * erf_q(fmaf(step, (float)(j + 1), zbase));
        float r[K];
        r[0] = h[0] + 0.5f;
#pragma unroll
        for (int j = 1; j < K - 1; j++) r[j] = h[j] - h[j - 1];
        r[K - 1] = 0.5f - h[K - 2];
        float4* o = reinterpret_cast<float4*>(out + ((size_t)b * Dn + d) * K);
        o[0] = make_float4(r[0],  r[1],  r[2],  r[3]);
        o[1] = make_float4(r[4],  r[5],  r[6],  r[7]);
        o[2] = make_float4(r[8],  r[9],  r[10], r[11]);
        o[3] = make_float4(r[12], r[13], r[14], r[15]);
    }
}

extern "C" void kernel_launch(void* const* d_in, const int* in_sizes, int n_in,
                              void* d_out, int out_size) {
    const float* mu = (const float*)d_in[0];
    const float* t  = (const float*)d_in[1];
    const float* W1 = (const float*)d_in[2];
    const float* b1 = (const float*)d_in[3];
    const float* W2 = (const float*)d_in[4];
    const float* b2 = (const float*)d_in[5];
    float* out = (float*)d_out;

    const int B = in_sizes[1];           // t has B elements
    const int D = in_sizes[0] / B;       // mu is [B, D]

    dim3 grid((D + TPB - 1) / TPB, B);
    bfn_kernel<<<grid, TPB>>>(mu, t, W1, b1, W2, b2, out, D);
}

// round 7
// speedup vs baseline: 2.7816x; 1.1535x over previous
#include <cuda_runtime.h>

// BayesianFlowNetworkDiscretised R6: per-row the MLP pipeline reduces to a 1-D
// function g_b(m) -> (zbase, step). Build kernel tabulates g_b (4096 pts/row,
// linear interp); main kernel = table lookup + R5's coalesced erf epilogue.

constexpr int K   = 16;
constexpr int H   = 16;
constexpr int TPB = 256;
constexpr int TN  = 4096;          // table entries per row
constexpr int BMAX = 64;           // max batch rows supported by static table
#define M_LO (-6.5f)
#define M_HI (6.5f)

__device__ float4 g_tab[BMAX * TN];   // (zb, dzb, st, dst) per entry

__device__ __forceinline__ float tanh_approx(float x) {
    float y;
    asm("tanh.approx.f32 %0, %1;" : "=f"(y) : "f"(x));
    return y;
}

// erf(z) ~= tanh(z * (C0 + C1 s + C2 s^2)), s = min(z^2, SCAP); max abs err ~2.2e-4
#define EQ_C0 1.1283792f
#define EQ_C1 0.104519f
#define EQ_C2 (-0.0020913f)
#define EQ_SCAP 22.0f

__device__ __forceinline__ float erf_q(float z) {
    const float s = fminf(z * z, EQ_SCAP);
    const float p = fmaf(fmaf(EQ_C2, s, EQ_C1), s, EQ_C0);
    return tanh_approx(z * p);
}

// ---------------- build kernel: tabulate g_b(m) ----------------

struct RowConst {
    float inv_gamma, vs, a0, be0, a1, be1;
    bool tmin;
};

__device__ __forceinline__ float2 eval_g(float m, const float4* sp, const RowConst& rc) {
    float acc0 = fmaf(m, rc.be0, rc.a0);
    float acc1 = fmaf(m, rc.be1, rc.a1);
#pragma unroll
    for (int j = 0; j < H; j++) {
        const float4 p = sp[j];
        const float a = fmaf(m, p.x, p.y);
        const float inner = a * fmaf(0.0356774081f, a * a, 0.7978845608f);
        const float ath = a * tanh_approx(inner);
        acc0 = fmaf(ath, p.z, acc0);
        acc1 = fmaf(ath, p.w, acc1);
    }
    float mu_x = fmaf(m, rc.inv_gamma, -rc.vs * acc0);
    float ln   = fminf(fmaxf(acc1, -10.0f), 10.0f);
    float sg   = fmaxf(rc.vs * __expf(ln), 0.02f);
    if (rc.tmin) { mu_x = 0.0f; sg = 1.0f; }
    const float inv = __fdividef(0.70710678118654752f, sg);
    return make_float2((-1.0f - mu_x) * inv, 0.125f * inv);
}

__global__ __launch_bounds__(TPB) void build_table(
    const float* __restrict__ t,
    const float* __restrict__ W1,
    const float* __restrict__ b1,
    const float* __restrict__ W2,
    const float* __restrict__ b2)
{
    __shared__ float4 s_pack[H];
    __shared__ float  s_scal[8];
    const int b = blockIdx.y;

    if (threadIdx.x < H) {
        const int j = threadIdx.x;
        const float tv = t[b];
        s_pack[j] = make_float4(W1[j],
                                fmaf(tv, W1[H + j], b1[j]),
                                0.5f * W2[2 * j],
                                0.5f * W2[2 * j + 1]);
        if (j == 0) {
            const float g = 1.0f - exp2f(2.0f * tv * -5.6438561897747395f);
            s_scal[0] = 1.0f / g;
            s_scal[1] = sqrtf((1.0f - g) / g);
            s_scal[2] = (tv < 1e-6f) ? 1.0f : 0.0f;
        }
    }
    __syncthreads();
    if (threadIdx.x == 0) {
        float a0 = b2[0], a1v = b2[1], be0 = 0.0f, be1 = 0.0f;
#pragma unroll
        for (int j = 0; j < H; j++) {
            const float4 p = s_pack[j];
            a0  = fmaf(p.y, p.z, a0);
            a1v = fmaf(p.y, p.w, a1v);
            be0 = fmaf(p.x, p.z, be0);
            be1 = fmaf(p.x, p.w, be1);
        }
        s_scal[3] = a0;  s_scal[4] = be0;
        s_scal[5] = a1v; s_scal[6] = be1;
    }
    __syncthreads();

    RowConst rc;
    rc.inv_gamma = s_scal[0]; rc.vs = s_scal[1];
    rc.tmin = s_scal[2] > 0.5f;
    rc.a0 = s_scal[3]; rc.be0 = s_scal[4];
    rc.a1 = s_scal[5]; rc.be1 = s_scal[6];

    const float dm = (M_HI - M_LO) / (float)(TN - 1);
    const int i0 = blockIdx.x * (TN / gridDim.x);
    const int i1 = i0 + (TN / gridDim.x);
    for (int i = i0 + threadIdx.x; i < i1; i += TPB) {
        const float m0 = M_LO + dm * (float)i;
        const float2 g0 = eval_g(m0, s_pack, rc);
        const float2 g1 = eval_g(m0 + dm, s_pack, rc);
        g_tab[b * TN + i] = make_float4(g0.x, g1.x - g0.x, g0.y, g1.y - g0.y);
    }
}

// ---------------- main kernel: lookup + coalesced erf epilogue ----------------

__global__ __launch_bounds__(TPB) void bfn_main(
    const float* __restrict__ mu,
    float* __restrict__ out,
    int Dn)
{
    __shared__ float2 s_zs[TPB];

    const int b = blockIdx.y;
    const int d = blockIdx.x * TPB + threadIdx.x;
    const bool active = (d < Dn);
    const int dclamp = active ? d : (Dn - 1);
    const float m = mu[(size_t)b * Dn + dclamp];

    // phase 1: table lookup with linear interpolation
    const float TSCALE = (float)(TN - 1) / (M_HI - M_LO);
    float u = (m - M_LO) * TSCALE;
    u = fminf(fmaxf(u, 0.0f), (float)(TN - 1) - 1e-3f);
    const float fl = floorf(u);
    const float fr = u - fl;
    const float4 e = __ldg(&g_tab[b * TN + (int)fl]);
    const float zbase = fmaf(fr, e.y, e.x);
    const float step  = fmaf(fr, e.w, e.z);

    // phase 2: warp remap via smem, coalesced float4 stores (as R5)
    const int lane    = threadIdx.x & 31;
    const int wbase_t = threadIdx.x & ~31;
    const int warp_d0 = blockIdx.x * TPB + wbase_t;

    s_zs[threadIdx.x] = make_float2(zbase, step);
    __syncwarp();

    if (warp_d0 + 32 <= Dn) {
        const int q = lane & 3;
        const float kq = (float)(q << 2);
        const float k1 = kq + 1.0f, k2 = kq + 2.0f, k3 = kq + 3.0f, k4 = kq + 4.0f;
        const bool q0 = (q == 0), q3 = (q == 3);
        float4* wout = reinterpret_cast<float4*>(out)
                     + ((size_t)b * Dn + warp_d0) * 4 + lane;
        const int src = wbase_t + (lane >> 2);

#pragma unroll
        for (int it = 0; it < 4; it++) {
            const float2 zs = s_zs[src + it * 8];
            const float zb = zs.x, st = zs.y;

            const float e1 = erf_q(fmaf(st, k1, zb));
            const float e2 = erf_q(fmaf(st, k2, zb));
            const float e3 = erf_q(fmaf(st, k3, zb));
            const float e4 = erf_q(fmaf(st, k4, zb));

            const float h1 = 0.5f * e1;
            const float h2 = 0.5f * e2;
            const float h3 = 0.5f * e3;
            float h4 = q3 ? 0.5f : 0.5f * e4;           // upper edge exact

            const float hup = __shfl_up_sync(0xffffffffu, h4, 1);
            const float h0 = q0 ? -0.5f : hup;          // lower edge exact

            wout[it * 32] = make_float4(h1 - h0, h2 - h1, h3 - h2, h4 - h3);
        }
    } else if (active) {
        // tail path (D%32==0 in practice)
        float h[K - 1];
#pragma unroll
        for (int j = 0; j < K - 1; j++)
            h[j] = 0.5f * erf_q(fmaf(step, (float)(j + 1), zbase));
        float r[K];
        r[0] = h[0] + 0.5f;
#pragma unroll
        for (int j = 1; j < K - 1; j++) r[j] = h[j] - h[j - 1];
        r[K - 1] = 0.5f - h[K - 2];
        float4* o = reinterpret_cast<float4*>(out + ((size_t)b * Dn + d) * K);
        o[0] = make_float4(r[0],  r[1],  r[2],  r[3]);
        o[1] = make_float4(r[4],  r[5],  r[6],  r[7]);
        o[2] = make_float4(r[8],  r[9],  r[10], r[11]);
        o[3] = make_float4(r[12], r[13], r[14], r[15]);
    }
}

extern "C" void kernel_launch(void* const* d_in, const int* in_sizes, int n_in,
                              void* d_out, int out_size) {
    const float* mu = (const float*)d_in[0];
    const float* t  = (const float*)d_in[1];
    const float* W1 = (const float*)d_in[2];
    const float* b1 = (const float*)d_in[3];
    const float* W2 = (const float*)d_in[4];
    const float* b2 = (const float*)d_in[5];
    float* out = (float*)d_out;

    const int B = in_sizes[1];           // t has B elements
    const int D = in_sizes[0] / B;       // mu is [B, D]
    const int Bc = (B <= BMAX) ? B : BMAX;

    dim3 bgrid(4, Bc);                   // 4 x-blocks per row over TN entries
    build_table<<<bgrid, TPB>>>(t, W1, b1, W2, b2);

    dim3 grid((D + TPB - 1) / TPB, B);
    bfn_main<<<grid, TPB>>>(mu, out, D);
}

// round 8
// speedup vs baseline: 2.8317x; 1.0180x over previous
#include <cuda_runtime.h>

// BayesianFlowNetworkDiscretised R7: tabulated g_b(m) -> (zbase, step), EPT=2
// main kernel (float2 mu loads, 2 gathers in flight), coalesced erf epilogue.

constexpr int K   = 16;
constexpr int H   = 16;
constexpr int TPB = 256;
constexpr int EPT = 2;                 // elements per thread (main)
constexpr int EPB = TPB * EPT;         // 512 elements per block
constexpr int TN  = 4096;              // table entries per row
constexpr int BMAX = 64;
#define M_LO (-6.5f)
#define M_HI (6.5f)

__device__ float4 g_tab[BMAX * TN];    // (zb, dzb, st, dst)

__device__ __forceinline__ float tanh_approx(float x) {
    float y;
    asm("tanh.approx.f32 %0, %1;" : "=f"(y) : "f"(x));
    return y;
}

// erf(z) ~= tanh(z*(C0+C1 s+C2 s^2)), s=min(z^2,SCAP); max abs err ~2.2e-4
#define EQ_C0 1.1283792f
#define EQ_C1 0.104519f
#define EQ_C2 (-0.0020913f)
#define EQ_SCAP 22.0f

__device__ __forceinline__ float erf_q(float z) {
    const float s = fminf(z * z, EQ_SCAP);
    const float p = fmaf(fmaf(EQ_C2, s, EQ_C1), s, EQ_C0);
    return tanh_approx(z * p);
}

// ---------------- build kernel ----------------

struct RowConst { float inv_gamma, vs, a0, be0, a1, be1; bool tmin; };

__device__ __forceinline__ float2 eval_g(float m, const float4* sp, const RowConst& rc) {
    float acc0 = fmaf(m, rc.be0, rc.a0);
    float acc1 = fmaf(m, rc.be1, rc.a1);
#pragma unroll
    for (int j = 0; j < H; j++) {
        const float4 p = sp[j];
        const float a = fmaf(m, p.x, p.y);
        const float inner = a * fmaf(0.0356774081f, a * a, 0.7978845608f);
        const float ath = a * tanh_approx(inner);
        acc0 = fmaf(ath, p.z, acc0);
        acc1 = fmaf(ath, p.w, acc1);
    }
    float mu_x = fmaf(m, rc.inv_gamma, -rc.vs * acc0);
    float ln   = fminf(fmaxf(acc1, -10.0f), 10.0f);
    float sg   = fmaxf(rc.vs * __expf(ln), 0.02f);
    if (rc.tmin) { mu_x = 0.0f; sg = 1.0f; }
    const float inv = __fdividef(0.70710678118654752f, sg);
    return make_float2((-1.0f - mu_x) * inv, 0.125f * inv);
}

__global__ __launch_bounds__(TPB) void build_table(
    const float* __restrict__ t,
    const float* __restrict__ W1,
    const float* __restrict__ b1,
    const float* __restrict__ W2,
    const float* __restrict__ b2)
{
    __shared__ float4 s_pack[H];
    __shared__ float  s_scal[8];
    __shared__ float2 s_e[TPB];
    const int b = blockIdx.y;

    if (threadIdx.x < H) {
        const int j = threadIdx.x;
        const float tv = t[b];
        s_pack[j] = make_float4(W1[j],
                                fmaf(tv, W1[H + j], b1[j]),
                                0.5f * W2[2 * j],
                                0.5f * W2[2 * j + 1]);
        if (j == 0) {
            const float g = 1.0f - exp2f(2.0f * tv * -5.6438561897747395f);
            s_scal[0] = 1.0f / g;
            s_scal[1] = sqrtf((1.0f - g) / g);
            s_scal[2] = (tv < 1e-6f) ? 1.0f : 0.0f;
        }
    }
    __syncthreads();
    if (threadIdx.x == 0) {
        float a0 = b2[0], a1v = b2[1], be0 = 0.0f, be1 = 0.0f;
#pragma unroll
        for (int j = 0; j < H; j++) {
            const float4 p = s_pack[j];
            a0  = fmaf(p.y, p.z, a0);
            a1v = fmaf(p.y, p.w, a1v);
            be0 = fmaf(p.x, p.z, be0);
            be1 = fmaf(p.x, p.w, be1);
        }
        s_scal[3] = a0;  s_scal[4] = be0;
        s_scal[5] = a1v; s_scal[6] = be1;
    }
    __syncthreads();

    RowConst rc;
    rc.inv_gamma = s_scal[0]; rc.vs = s_scal[1];
    rc.tmin = s_scal[2] > 0.5f;
    rc.a0 = s_scal[3]; rc.be0 = s_scal[4];
    rc.a1 = s_scal[5]; rc.be1 = s_scal[6];

    const float dm = (M_HI - M_LO) / (float)(TN - 1);
    const int i = blockIdx.x * TPB + threadIdx.x;     // one entry per thread
    const float m0 = M_LO + dm * (float)i;
    const float2 g0 = eval_g(m0, s_pack, rc);
    s_e[threadIdx.x] = g0;
    __syncthreads();
    float2 g1 = (threadIdx.x < TPB - 1) ? s_e[threadIdx.x + 1]
                                        : eval_g(m0 + dm, s_pack, rc);
    g_tab[b * TN + i] = make_float4(g0.x, g1.x - g0.x, g0.y, g1.y - g0.y);
}

// ---------------- main kernel ----------------

__global__ __launch_bounds__(TPB) void bfn_main(
    const float* __restrict__ mu,
    float* __restrict__ out,
    int Dn)
{
    __shared__ float2 s_zs[EPB];

    const int b = blockIdx.y;
    const int blk0 = blockIdx.x * EPB;              // first element of block
    const int tid  = threadIdx.x;
    const int lane = tid & 31;
    const int wid  = tid >> 5;

    const float TSCALE = (float)(TN - 1) / (M_HI - M_LO);
    const float4* tab = g_tab + b * TN;

    const int d0 = blk0 + tid * EPT;
    const bool full_blk = (blk0 + EPB <= Dn);

    if (full_blk) {
        // phase 1: two elements, coalesced float2 load, 2 gathers in flight
        const float2 mv = *reinterpret_cast<const float2*>(
            mu + (size_t)b * Dn + d0);
#pragma unroll
        for (int e = 0; e < EPT; e++) {
            const float m = (e == 0) ? mv.x : mv.y;
            float u = (m - M_LO) * TSCALE;
            u = fminf(fmaxf(u, 0.0f), (float)(TN - 1) - 1e-3f);
            const int   idx = __float2int_rd(u);
            const float fr  = u - (float)idx;
            const float4 en = __ldg(&tab[idx]);
            s_zs[tid * EPT + e] = make_float2(fmaf(fr, en.y, en.x),
                                              fmaf(fr, en.w, en.z));
        }
        __syncwarp();

        // phase 2: warp owns 64 consecutive elements (its own phase-1 output)
        const int q = lane & 3;
        const float kq = (float)(q << 2);
        const float k1 = kq + 1.0f, k2 = kq + 2.0f, k3 = kq + 3.0f, k4 = kq + 4.0f;
        const bool q0 = (q == 0), q3 = (q == 3);
        const int we0 = wid * 64;                    // warp's first element in block
        float4* wout = reinterpret_cast<float4*>(out)
                     + ((size_t)b * Dn + blk0 + we0) * 4 + lane;
        const int src = we0 + (lane >> 2);

#pragma unroll
        for (int it = 0; it < 8; it++) {
            const float2 zs = s_zs[src + it * 8];
            const float zb = zs.x, st = zs.y;

            const float e1 = erf_q(fmaf(st, k1, zb));
            const float e2 = erf_q(fmaf(st, k2, zb));
            const float e3 = erf_q(fmaf(st, k3, zb));
            float e4 = erf_q(fmaf(st, k4, zb));
            if (q3) e4 = 1.0f;                       // upper edge exact

            const float eup = __shfl_up_sync(0xffffffffu, e4, 1);
            const float e0 = q0 ? -1.0f : eup;       // lower edge exact

            wout[it * 32] = make_float4(0.5f * (e1 - e0), 0.5f * (e2 - e1),
                                        0.5f * (e3 - e2), 0.5f * (e4 - e3));
        }
    } else {
        // tail block (not taken when D % EPB == 0): per-element scalar path
        for (int e = 0; e < EPT; e++) {
            const int d = d0 + e;
            if (d >= Dn) break;
            const float m = mu[(size_t)b * Dn + d];
            float u = (m - M_LO) * TSCALE;
            u = fminf(fmaxf(u, 0.0f), (float)(TN - 1) - 1e-3f);
            const int   idx = __float2int_rd(u);
            const float fr  = u - (float)idx;
            const float4 en = __ldg(&tab[idx]);
            const float zbase = fmaf(fr, en.y, en.x);
            const float step  = fmaf(fr, en.w, en.z);

            float h[K - 1];
#pragma unroll
            for (int j = 0; j < K - 1; j++)
                h[j] = 0.5f * erf_q(fmaf(step, (float)(j + 1), zbase));
            float r[K];
            r[0] = h[0] + 0.5f;
#pragma unroll
            for (int j = 1; j < K - 1; j++) r[j] = h[j] - h[j - 1];
            r[K - 1] = 0.5f - h[K - 2];
            float4* o = reinterpret_cast<float4*>(out + ((size_t)b * Dn + d) * K);
            o[0] = make_float4(r[0],  r[1],  r[2],  r[3]);
            o[1] = make_float4(r[4],  r[5],  r[6],  r[7]);
            o[2] = make_float4(r[8],  r[9],  r[10], r[11]);
            o[3] = make_float4(r[12], r[13], r[14], r[15]);
        }
    }
}

extern "C" void kernel_launch(void* const* d_in, const int* in_sizes, int n_in,
                              void* d_out, int out_size) {
    const float* mu = (const float*)d_in[0];
    const float* t  = (const float*)d_in[1];
    const float* W1 = (const float*)d_in[2];
    const float* b1 = (const float*)d_in[3];
    const float* W2 = (const float*)d_in[4];
    const float* b2 = (const float*)d_in[5];
    float* out = (float*)d_out;

    const int B = in_sizes[1];           // t has B elements
    const int D = in_sizes[0] / B;       // mu is [B, D]
    const int Bc = (B <= BMAX) ? B : BMAX;

    dim3 bgrid(TN / TPB, Bc);            // 16 x-blocks per row, 1 entry/thread
    build_table<<<bgrid, TPB>>>(t, W1, b1, W2, b2);

    dim3 grid((D + EPB - 1) / EPB, B);
    bfn_main<<<grid, TPB>>>(mu, out, D);
}

// round 9
// speedup vs baseline: 3.0439x; 1.0749x over previous
#include <cuda_runtime.h>

// BayesianFlowNetworkDiscretised R8: tabulated g_b(m) with TN=1024 so the hot
// table working set is L1-resident (fixes R7's L2-latency-bound gather).
// Cubic erf poly restores accuracy lost to the coarser table.

constexpr int K   = 16;
constexpr int H   = 16;
constexpr int TPB = 256;
constexpr int EPT = 2;                 // elements per thread (main)
constexpr int EPB = TPB * EPT;         // 512 elements per block
constexpr int TN  = 1024;              // table entries per row (L1-resident hot set)
constexpr int BMAX = 64;
#define M_LO (-6.5f)
#define M_HI (6.5f)

__device__ float4 g_tab[BMAX * TN];    // (zb, dzb, st, dst)

__device__ __forceinline__ float tanh_approx(float x) {
    float y;
    asm("tanh.approx.f32 %0, %1;" : "=f"(y) : "f"(x));
    return y;
}

// erf(z) ~= tanh(z*(C0+C1 s+C2 s^2+C3 s^3)), s=min(z^2,SCAP); max abs err ~7e-5
#define ERF_C0 1.1283792f
#define ERF_C1 0.1038252f
#define ERF_C2 (-0.00176024f)
#define ERF_C3 (-2.46588e-5f)
#define ERF_SCAP 15.3664f

__device__ __forceinline__ float erf_c(float z) {
    const float s = fminf(z * z, ERF_SCAP);
    const float p = fmaf(fmaf(fmaf(ERF_C3, s, ERF_C2), s, ERF_C1), s, ERF_C0);
    return tanh_approx(z * p);
}

// ---------------- build kernel ----------------

struct RowConst { float inv_gamma, vs, a0, be0, a1, be1; bool tmin; };

__device__ __forceinline__ float2 eval_g(float m, const float4* sp, const RowConst& rc) {
    float acc0 = fmaf(m, rc.be0, rc.a0);
    float acc1 = fmaf(m, rc.be1, rc.a1);
#pragma unroll
    for (int j = 0; j < H; j++) {
        const float4 p = sp[j];
        const float a = fmaf(m, p.x, p.y);
        const float inner = a * fmaf(0.0356774081f, a * a, 0.7978845608f);
        const float ath = a * tanh_approx(inner);
        acc0 = fmaf(ath, p.z, acc0);
        acc1 = fmaf(ath, p.w, acc1);
    }
    float mu_x = fmaf(m, rc.inv_gamma, -rc.vs * acc0);
    float ln   = fminf(fmaxf(acc1, -10.0f), 10.0f);
    float sg   = fmaxf(rc.vs * __expf(ln), 0.02f);
    if (rc.tmin) { mu_x = 0.0f; sg = 1.0f; }
    const float inv = __fdividef(0.70710678118654752f, sg);
    return make_float2((-1.0f - mu_x) * inv, 0.125f * inv);
}

__global__ __launch_bounds__(TPB) void build_table(
    const float* __restrict__ t,
    const float* __restrict__ W1,
    const float* __restrict__ b1,
    const float* __restrict__ W2,
    const float* __restrict__ b2)
{
    __shared__ float4 s_pack[H];
    __shared__ float  s_scal[8];
    __shared__ float2 s_e[TPB];
    const int b = blockIdx.y;

    if (threadIdx.x < H) {
        const int j = threadIdx.x;
        const float tv = t[b];
        s_pack[j] = make_float4(W1[j],
                                fmaf(tv, W1[H + j], b1[j]),
                                0.5f * W2[2 * j],
                                0.5f * W2[2 * j + 1]);
        if (j == 0) {
            const float g = 1.0f - exp2f(2.0f * tv * -5.6438561897747395f);
            s_scal[0] = 1.0f / g;
            s_scal[1] = sqrtf((1.0f - g) / g);
            s_scal[2] = (tv < 1e-6f) ? 1.0f : 0.0f;
        }
    }
    __syncthreads();
    if (threadIdx.x == 0) {
        float a0 = b2[0], a1v = b2[1], be0 = 0.0f, be1 = 0.0f;
#pragma unroll
        for (int j = 0; j < H; j++) {
            const float4 p = s_pack[j];
            a0  = fmaf(p.y, p.z, a0);
            a1v = fmaf(p.y, p.w, a1v);
            be0 = fmaf(p.x, p.z, be0);
            be1 = fmaf(p.x, p.w, be1);
        }
        s_scal[3] = a0;  s_scal[4] = be0;
        s_scal[5] = a1v; s_scal[6] = be1;
    }
    __syncthreads();

    RowConst rc;
    rc.inv_gamma = s_scal[0]; rc.vs = s_scal[1];
    rc.tmin = s_scal[2] > 0.5f;
    rc.a0 = s_scal[3]; rc.be0 = s_scal[4];
    rc.a1 = s_scal[5]; rc.be1 = s_scal[6];

    const float dm = (M_HI - M_LO) / (float)(TN - 1);
    const int i = blockIdx.x * TPB + threadIdx.x;     // one entry per thread
    const float m0 = M_LO + dm * (float)i;
    const float2 g0 = eval_g(m0, s_pack, rc);
    s_e[threadIdx.x] = g0;
    __syncthreads();
    float2 g1 = (threadIdx.x < TPB - 1) ? s_e[threadIdx.x + 1]
                                        : eval_g(m0 + dm, s_pack, rc);
    g_tab[b * TN + i] = make_float4(g0.x, g1.x - g0.x, g0.y, g1.y - g0.y);
}

// ---------------- main kernel ----------------

__global__ __launch_bounds__(TPB) void bfn_main(
    const float* __restrict__ mu,
    float* __restrict__ out,
    int Dn)
{
    __shared__ float2 s_zs[EPB];

    const int b = blockIdx.y;
    const int blk0 = blockIdx.x * EPB;
    const int tid  = threadIdx.x;
    const int lane = tid & 31;
    const int wid  = tid >> 5;

    const float TSCALE = (float)(TN - 1) / (M_HI - M_LO);
    const float4* tab = g_tab + b * TN;

    const int d0 = blk0 + tid * EPT;
    const bool full_blk = (blk0 + EPB <= Dn);

    if (full_blk) {
        const float2 mv = *reinterpret_cast<const float2*>(
            mu + (size_t)b * Dn + d0);
#pragma unroll
        for (int e = 0; e < EPT; e++) {
            const float m = (e == 0) ? mv.x : mv.y;
            float u = (m - M_LO) * TSCALE;
            u = fminf(fmaxf(u, 0.0f), (float)(TN - 1) - 1e-3f);
            const int   idx = __float2int_rd(u);
            const float fr  = u - (float)idx;
            const float4 en = __ldg(&tab[idx]);
            s_zs[tid * EPT + e] = make_float2(fmaf(fr, en.y, en.x),
                                              fmaf(fr, en.w, en.z));
        }
        __syncwarp();

        const int q = lane & 3;
        const float kq = (float)(q << 2);
        const float k1 = kq + 1.0f, k2 = kq + 2.0f, k3 = kq + 3.0f, k4 = kq + 4.0f;
        const bool q0 = (q == 0), q3 = (q == 3);
        const int we0 = wid * 64;
        float4* wout = reinterpret_cast<float4*>(out)
                     + ((size_t)b * Dn + blk0 + we0) * 4 + lane;
        const int src = we0 + (lane >> 2);

#pragma unroll
        for (int it = 0; it < 8; it++) {
            const float2 zs = s_zs[src + it * 8];
            const float zb = zs.x, st = zs.y;

            const float e1 = erf_c(fmaf(st, k1, zb));
            const float e2 = erf_c(fmaf(st, k2, zb));
            const float e3 = erf_c(fmaf(st, k3, zb));
            float e4 = erf_c(fmaf(st, k4, zb));
            if (q3) e4 = 1.0f;                       // upper edge exact

            const float eup = __shfl_up_sync(0xffffffffu, e4, 1);
            const float e0 = q0 ? -1.0f : eup;       // lower edge exact

            wout[it * 32] = make_float4(0.5f * (e1 - e0), 0.5f * (e2 - e1),
                                        0.5f * (e3 - e2), 0.5f * (e4 - e3));
        }
    } else {
        for (int e = 0; e < EPT; e++) {
            const int d = d0 + e;
            if (d >= Dn) break;
            const float m = mu[(size_t)b * Dn + d];
            float u = (m - M_LO) * TSCALE;
            u = fminf(fmaxf(u, 0.0f), (float)(TN - 1) - 1e-3f);
            const int   idx = __float2int_rd(u);
            const float fr  = u - (float)idx;
            const float4 en = __ldg(&tab[idx]);
            const float zbase = fmaf(fr, en.y, en.x);
            const float step  = fmaf(fr, en.w, en.z);

            float h[K - 1];
#pragma unroll
            for (int j = 0; j < K - 1; j++)
                h[j] = 0.5f * erf_c(fmaf(step, (float)(j + 1), zbase));
            float r[K];
            r[0] = h[0] + 0.5f;
#pragma unroll
            for (int j = 1; j < K - 1; j++) r[j] = h[j] - h[j - 1];
            r[K - 1] = 0.5f - h[K - 2];
            float4* o = reinterpret_cast<float4*>(out + ((size_t)b * Dn + d) * K);
            o[0] = make_float4(r[0],  r[1],  r[2],  r[3]);
            o[1] = make_float4(r[4],  r[5],  r[6],  r[7]);
            o[2] = make_float4(r[8],  r[9],  r[10], r[11]);
            o[3] = make_float4(r[12], r[13], r[14], r[15]);
        }
    }
}

extern "C" void kernel_launch(void* const* d_in, const int* in_sizes, int n_in,
                              void* d_out, int out_size) {
    const float* mu = (const float*)d_in[0];
    const float* t  = (const float*)d_in[1];
    const float* W1 = (const float*)d_in[2];
    const float* b1 = (const float*)d_in[3];
    const float* W2 = (const float*)d_in[4];
    const float* b2 = (const float*)d_in[5];
    float* out = (float*)d_out;

    const int B = in_sizes[1];           // t has B elements
    const int D = in_sizes[0] / B;       // mu is [B, D]
    const int Bc = (B <= BMAX) ? B : BMAX;

    dim3 bgrid(TN / TPB, Bc);            // 4 x-blocks per row, 1 entry/thread
    build_table<<<bgrid, TPB>>>(t, W1, b1, W2, b2);

    dim3 grid((D + EPB - 1) / EPB, B);
    bfn_main<<<grid, TPB>>>(mu, out, D);
}

// round 11
// speedup vs baseline: 3.0558x; 1.0039x over previous
#include <cuda_runtime.h>

// BayesianFlowNetworkDiscretised R10: R8 (TN=1024 L1-resident table, cubic erf)
// + PDL with checked fallback: if cudaLaunchKernelEx(PDL) fails, fall back to a
// plain launch (device-side GridDependencySynchronize is a no-op then).

constexpr int K   = 16;
constexpr int H   = 16;
constexpr int TPB = 256;
constexpr int EPT = 2;                 // elements per thread (main)
constexpr int EPB = TPB * EPT;         // 512 elements per block
constexpr int TN  = 1024;              // table entries per row
constexpr int BMAX = 64;
#define M_LO (-6.5f)
#define M_HI (6.5f)

__device__ float4 g_tab[BMAX * TN];    // (zb, dzb, st, dst)

__device__ __forceinline__ float tanh_approx(float x) {
    float y;
    asm("tanh.approx.f32 %0, %1;" : "=f"(y) : "f"(x));
    return y;
}

// erf(z) ~= tanh(z*(C0+C1 s+C2 s^2+C3 s^3)), s=min(z^2,SCAP); max abs err ~7e-5
#define ERF_C0 1.1283792f
#define ERF_C1 0.1038252f
#define ERF_C2 (-0.00176024f)
#define ERF_C3 (-2.46588e-5f)
#define ERF_SCAP 15.3664f

__device__ __forceinline__ float erf_c(float z) {
    const float s = fminf(z * z, ERF_SCAP);
    const float p = fmaf(fmaf(fmaf(ERF_C3, s, ERF_C2), s, ERF_C1), s, ERF_C0);
    return tanh_approx(z * p);
}

// ---------------- build kernel ----------------

struct RowConst { float inv_gamma, vs, a0, be0, a1, be1; bool tmin; };

__device__ __forceinline__ float2 eval_g(float m, const float4* sp, const RowConst& rc) {
    float acc0 = fmaf(m, rc.be0, rc.a0);
    float acc1 = fmaf(m, rc.be1, rc.a1);
#pragma unroll
    for (int j = 0; j < H; j++) {
        const float4 p = sp[j];
        const float a = fmaf(m, p.x, p.y);
        const float inner = a * fmaf(0.0356774081f, a * a, 0.7978845608f);
        const float ath = a * tanh_approx(inner);
        acc0 = fmaf(ath, p.z, acc0);
        acc1 = fmaf(ath, p.w, acc1);
    }
    float mu_x = fmaf(m, rc.inv_gamma, -rc.vs * acc0);
    float ln   = fminf(fmaxf(acc1, -10.0f), 10.0f);
    float sg   = fmaxf(rc.vs * __expf(ln), 0.02f);
    if (rc.tmin) { mu_x = 0.0f; sg = 1.0f; }
    const float inv = __fdividef(0.70710678118654752f, sg);
    return make_float2((-1.0f - mu_x) * inv, 0.125f * inv);
}

__global__ __launch_bounds__(TPB) void build_table(
    const float* __restrict__ t,
    const float* __restrict__ W1,
    const float* __restrict__ b1,
    const float* __restrict__ W2,
    const float* __restrict__ b2)
{
    __shared__ float4 s_pack[H];
    __shared__ float  s_scal[8];
    __shared__ float2 s_e[TPB];
    const int b = blockIdx.y;

    if (threadIdx.x < H) {
        const int j = threadIdx.x;
        const float tv = t[b];
        s_pack[j] = make_float4(W1[j],
                                fmaf(tv, W1[H + j], b1[j]),
                                0.5f * W2[2 * j],
                                0.5f * W2[2 * j + 1]);
        if (j == 0) {
            const float g = 1.0f - exp2f(2.0f * tv * -5.6438561897747395f);
            s_scal[0] = 1.0f / g;
            s_scal[1] = sqrtf((1.0f - g) / g);
            s_scal[2] = (tv < 1e-6f) ? 1.0f : 0.0f;
        }
    }
    __syncthreads();
    if (threadIdx.x == 0) {
        float a0 = b2[0], a1v = b2[1], be0 = 0.0f, be1 = 0.0f;
#pragma unroll
        for (int j = 0; j < H; j++) {
            const float4 p = s_pack[j];
            a0  = fmaf(p.y, p.z, a0);
            a1v = fmaf(p.y, p.w, a1v);
            be0 = fmaf(p.x, p.z, be0);
            be1 = fmaf(p.x, p.w, be1);
        }
        s_scal[3] = a0;  s_scal[4] = be0;
        s_scal[5] = a1v; s_scal[6] = be1;
    }
    __syncthreads();

    RowConst rc;
    rc.inv_gamma = s_scal[0]; rc.vs = s_scal[1];
    rc.tmin = s_scal[2] > 0.5f;
    rc.a0 = s_scal[3]; rc.be0 = s_scal[4];
    rc.a1 = s_scal[5]; rc.be1 = s_scal[6];

    const float dm = (M_HI - M_LO) / (float)(TN - 1);
    const int i = blockIdx.x * TPB + threadIdx.x;     // one entry per thread
    const float m0 = M_LO + dm * (float)i;
    const float2 g0 = eval_g(m0, s_pack, rc);
    s_e[threadIdx.x] = g0;
    __syncthreads();
    float2 g1 = (threadIdx.x < TPB - 1) ? s_e[threadIdx.x + 1]
                                        : eval_g(m0 + dm, s_pack, rc);
    g_tab[b * TN + i] = make_float4(g0.x, g1.x - g0.x, g0.y, g1.y - g0.y);

#if __CUDA_ARCH__ >= 900
    cudaTriggerProgrammaticLaunchCompletion();
#endif
}

// ---------------- main kernel ----------------

__global__ __launch_bounds__(TPB) void bfn_main(
    const float* __restrict__ mu,
    float* __restrict__ out,
    int Dn)
{
    __shared__ float2 s_zs[EPB];

    const int b = blockIdx.y;
    const int blk0 = blockIdx.x * EPB;
    const int tid  = threadIdx.x;
    const int lane = tid & 31;
    const int wid  = tid >> 5;

    const float TSCALE = (float)(TN - 1) / (M_HI - M_LO);
    const float4* tab = g_tab + b * TN;

    const int d0 = blk0 + tid * EPT;
    const bool full_blk = (blk0 + EPB <= Dn);

    if (full_blk) {
        // mu load issued BEFORE the grid-dependency wait (overlap under PDL)
        const float2 mv = *reinterpret_cast<const float2*>(
            mu + (size_t)b * Dn + d0);
#if __CUDA_ARCH__ >= 900
        cudaGridDependencySynchronize();
#endif
#pragma unroll
        for (int e = 0; e < EPT; e++) {
            const float m = (e == 0) ? mv.x : mv.y;
            float u = (m - M_LO) * TSCALE;
            u = fminf(fmaxf(u, 0.0f), (float)(TN - 1) - 1e-3f);
            const int   idx = __float2int_rd(u);
            const float fr  = u - (float)idx;
            const float4 en = __ldg(&tab[idx]);
            s_zs[tid * EPT + e] = make_float2(fmaf(fr, en.y, en.x),
                                              fmaf(fr, en.w, en.z));
        }
        __syncwarp();

        const int q = lane & 3;
        const float kq = (float)(q << 2);
        const float k1 = kq + 1.0f, k2 = kq + 2.0f, k3 = kq + 3.0f, k4 = kq + 4.0f;
        const bool q0 = (q == 0), q3 = (q == 3);
        const int we0 = wid * 64;
        float4* wout = reinterpret_cast<float4*>(out)
                     + ((size_t)b * Dn + blk0 + we0) * 4 + lane;
        const int src = we0 + (lane >> 2);

#pragma unroll
        for (int it = 0; it < 8; it++) {
            const float2 zs = s_zs[src + it * 8];
            const float zb = zs.x, st = zs.y;

            const float e1 = erf_c(fmaf(st, k1, zb));
            const float e2 = erf_c(fmaf(st, k2, zb));
            const float e3 = erf_c(fmaf(st, k3, zb));
            float e4 = erf_c(fmaf(st, k4, zb));
            if (q3) e4 = 1.0f;                       // upper edge exact

            const float eup = __shfl_up_sync(0xffffffffu, e4, 1);
            const float e0 = q0 ? -1.0f : eup;       // lower edge exact

            wout[it * 32] = make_float4(0.5f * (e1 - e0), 0.5f * (e2 - e1),
                                        0.5f * (e3 - e2), 0.5f * (e4 - e3));
        }
    } else {
#if __CUDA_ARCH__ >= 900
        cudaGridDependencySynchronize();
#endif
        for (int e = 0; e < EPT; e++) {
            const int d = d0 + e;
            if (d >= Dn) break;
            const float m = mu[(size_t)b * Dn + d];
            float u = (m - M_LO) * TSCALE;
            u = fminf(fmaxf(u, 0.0f), (float)(TN - 1) - 1e-3f);
            const int   idx = __float2int_rd(u);
            const float fr  = u - (float)idx;
            const float4 en = __ldg(&tab[idx]);
            const float zbase = fmaf(fr, en.y, en.x);
            const float step  = fmaf(fr, en.w, en.z);

            float h[K - 1];
#pragma unroll
            for (int j = 0; j < K - 1; j++)
                h[j] = 0.5f * erf_c(fmaf(step, (float)(j + 1), zbase));
            float r[K];
            r[0] = h[0] + 0.5f;
#pragma unroll
            for (int j = 1; j < K - 1; j++) r[j] = h[j] - h[j - 1];
            r[K - 1] = 0.5f - h[K - 2];
            float4* o = reinterpret_cast<float4*>(out + ((size_t)b * Dn + d) * K);
            o[0] = make_float4(r[0],  r[1],  r[2],  r[3]);
            o[1] = make_float4(r[4],  r[5],  r[6],  r[7]);
            o[2] = make_float4(r[8],  r[9],  r[10], r[11]);
            o[3] = make_float4(r[12], r[13], r[14], r[15]);
        }
    }
}

extern "C" void kernel_launch(void* const* d_in, const int* in_sizes, int n_in,
                              void* d_out, int out_size) {
    const float* mu = (const float*)d_in[0];
    const float* t  = (const float*)d_in[1];
    const float* W1 = (const float*)d_in[2];
    const float* b1 = (const float*)d_in[3];
    const float* W2 = (const float*)d_in[4];
    const float* b2 = (const float*)d_in[5];
    float* out = (float*)d_out;

    const int B = in_sizes[1];           // t has B elements
    const int D = in_sizes[0] / B;       // mu is [B, D]
    const int Bc = (B <= BMAX) ? B : BMAX;

    dim3 bgrid(TN / TPB, Bc);
    build_table<<<bgrid, TPB>>>(t, W1, b1, W2, b2);

    dim3 grid((D + EPB - 1) / EPB, B);

    // Attempt PDL launch; on any error fall back to a plain launch (in which
    // case stream order alone guarantees correctness and device-side
    // GridDependencySynchronize is a no-op).
    cudaLaunchConfig_t cfg = {};
    cfg.gridDim = grid;
    cfg.blockDim = dim3(TPB, 1, 1);
    cfg.dynamicSmemBytes = 0;
    cfg.stream = 0;
    cudaLaunchAttribute attrs[1];
    attrs[0].id = cudaLaunchAttributeProgrammaticStreamSerialization;
    attrs[0].val.programmaticStreamSerializationAllowed = 1;
    cfg.attrs = attrs;
    cfg.numAttrs = 1;
    cudaError_t err = cudaLaunchKernelEx(&cfg, bfn_main, mu, out, D);
    if (err != cudaSuccess) {
        (void)cudaGetLastError();        // clear sticky error, then plain launch
        bfn_main<<<grid, TPB>>>(mu, out, D);
    }
}